// round 2
// baseline (speedup 1.0000x reference)
#include <cuda_runtime.h>
#include <math.h>
#include <float.h>

#define S_SLOTS 65536
#define DIM     512
#define BATCH   64

// ---------------- device scratch (static, no allocation) ----------------
__device__ float g_nn[BATCH * DIM];
__device__ float g_sims[(size_t)BATCH * S_SLOTS];     // 16 MB, layout [b*S + s]
__device__ float g_confdot[(size_t)S_SLOTS * 32];     // 8 MB,  layout [s*32 + j]
__device__ float g_norms[S_SLOTS];
__device__ float g_erase[S_SLOTS];
__device__ float g_maskedpre[S_SLOTS];
__device__ float g_slotage[S_SLOTS];
__device__ float g_novelty[BATCH];
__device__ float g_storev[BATCH];
__device__ int   g_ti[BATCH * 3];
__device__ float g_tv[BATCH * 3];
__device__ float g_prob[BATCH * 3];
__device__ float g_strength[BATCH * 3];
__device__ int   g_apply[BATCH * 3];
__device__ float g_drifted0[DIM];
__device__ int   g_chg[256];
__device__ int   g_nchg;
__device__ float g_rowsum[256];

struct Scalars {
    float stepf;
    int   n_active;
    unsigned int age_max_bits;
    unsigned long long victim_pack;
    int   cond_count;
    unsigned int masked_max_bits;
    unsigned long long wmax_pack;
    // finalized
    int   do_erase;
    int   victim;
    float capacity;
    float dyn_thr, topk_thr, raw_thr;
    float nov_mean;
    int   should_store;
    int   use_slotage;
    int   write_idx;
};
__device__ Scalars g_s;

__device__ __forceinline__ float sigf(float x) { return 1.0f / (1.0f + expf(-x)); }

// ---------------- reset / scalar init ----------------
__global__ void k_reset(const void* step_ptr) {
    int   iv = *(const int*)step_ptr;
    float fv = *(const float*)step_ptr;
    g_s.stepf = (iv > 0 && iv < 100000000) ? (float)iv : fv;
    g_s.n_active = 0;
    g_s.age_max_bits = 0u;
    g_s.victim_pack = 0ull;
    g_s.cond_count = 0;
    g_s.masked_max_bits = 0u;
    g_s.wmax_pack = 0ull;
}

// ---------------- normalize new_content ----------------
__global__ void k_normalize(const float* __restrict__ nc) {
    int b = blockIdx.x, t = threadIdx.x;   // 128 threads
    __shared__ float red[128];
    float s = 0.f;
    for (int i = t; i < DIM; i += 128) { float v = nc[b * DIM + i]; s += v * v; }
    red[t] = s; __syncthreads();
    for (int off = 64; off > 0; off >>= 1) { if (t < off) red[t] += red[t + off]; __syncthreads(); }
    float inv = 1.0f / fmaxf(sqrtf(red[0]), 1e-12f);
    for (int i = t; i < DIM; i += 128) g_nn[b * DIM + i] = nc[b * DIM + i] * inv;
}

// ---------------- main fused pass: copy mem->out, norms, sims(64), confdot(32) ----------------
// GEMM: [S x 512] @ [512 x 96], 128 rows per block, 192 threads, 8x8 reg tile.
__global__ void __launch_bounds__(192) k_main(const float* __restrict__ mem,
                                              const float* __restrict__ ec_w,
                                              float* __restrict__ out_mem) {
    __shared__ float As[32][128];
    __shared__ float Bs[32][96];
    __shared__ float nsh[128];
    const int t  = threadIdx.x;
    const int rg = t & 15;      // 0..15
    const int cg = t >> 4;      // 0..11
    const int row0 = blockIdx.x * 128;

    float acc[8][8];
#pragma unroll
    for (int i = 0; i < 8; i++)
#pragma unroll
        for (int j = 0; j < 8; j++) acc[i][j] = 0.f;
    float sq[8] = {0.f,0.f,0.f,0.f,0.f,0.f,0.f,0.f};
    const bool donorm = (cg == 0);

    for (int kc = 0; kc < DIM; kc += 32) {
        // load A tile (128 rows x 32 k) as float4, and stream copy to out
        for (int i = t; i < 1024; i += 192) {
            int r = i >> 3;
            int f = i & 7;
            size_t goff = (size_t)(row0 + r) * DIM + kc + f * 4;
            float4 v = *(const float4*)(mem + goff);
            *(float4*)(out_mem + goff) = v;
            As[f * 4 + 0][r] = v.x; As[f * 4 + 1][r] = v.y;
            As[f * 4 + 2][r] = v.z; As[f * 4 + 3][r] = v.w;
        }
        // load B tile (32 k x 96 cols): cols 0..63 = g_nn rows, 64..95 = ec_w cols
        for (int i = t; i < 32 * 96; i += 192) {
            int kk = i / 96, c = i - kk * 96;
            int k = kc + kk;
            float v = (c < 64) ? g_nn[c * DIM + k] : ec_w[k * 32 + (c - 64)];
            Bs[kk][c] = v;
        }
        __syncthreads();
#pragma unroll 8
        for (int kk = 0; kk < 32; kk++) {
            float a[8], bb[8];
#pragma unroll
            for (int i = 0; i < 8; i++) a[i] = As[kk][rg + i * 16];
#pragma unroll
            for (int j = 0; j < 8; j++) bb[j] = Bs[kk][cg * 8 + j];
#pragma unroll
            for (int i = 0; i < 8; i++)
#pragma unroll
                for (int j = 0; j < 8; j++) acc[i][j] = fmaf(a[i], bb[j], acc[i][j]);
            if (donorm) {
#pragma unroll
                for (int i = 0; i < 8; i++) sq[i] = fmaf(a[i], a[i], sq[i]);
            }
        }
        __syncthreads();
    }
    if (donorm) {
#pragma unroll
        for (int i = 0; i < 8; i++) {
            int r = rg + i * 16;
            float n = sqrtf(sq[i]);
            nsh[r] = n;
            g_norms[row0 + r] = n;
        }
    }
    __syncthreads();
#pragma unroll
    for (int i = 0; i < 8; i++) {
        int r = rg + i * 16;
        int s = row0 + r;
        float inv = 1.0f / fmaxf(nsh[r], 1e-12f);
#pragma unroll
        for (int j = 0; j < 8; j++) {
            int c = cg * 8 + j;
            if (c < 64) g_sims[(size_t)c * S_SLOTS + s] = acc[i][j] * inv;
            else        g_confdot[(size_t)s * 32 + (c - 64)] = acc[i][j];
        }
    }
}

// ---------------- reduce: n_active, age_max ----------------
__global__ void k_reduce1(const float* __restrict__ at) {
    int s = blockIdx.x * 256 + threadIdx.x;
    int t = threadIdx.x;
    __shared__ int shi[256];
    __shared__ unsigned shu[256];
    int active = (g_norms[s] > 0.5f) ? 1 : 0;
    float age = fmaxf(g_s.stepf - at[s], 0.f);
    shi[t] = active;
    shu[t] = __float_as_uint(age);   // nonneg float: uint order == float order
    __syncthreads();
    for (int off = 128; off > 0; off >>= 1) {
        if (t < off) {
            shi[t] += shi[t + off];
            if (shu[t + off] > shu[t]) shu[t] = shu[t + off];
        }
        __syncthreads();
    }
    if (t == 0) {
        atomicAdd(&g_s.n_active, shi[0]);
        atomicMax(&g_s.age_max_bits, shu[0]);
    }
}

// ---------------- victim argmax of es_em ----------------
__global__ void k_victim(const float* __restrict__ at) {
    int s = blockIdx.x * 256 + threadIdx.x;
    int t = threadIdx.x;
    __shared__ unsigned long long sh[256];
    float amax = __uint_as_float(g_s.age_max_bits);
    float age = fmaxf(g_s.stepf - at[s], 0.f);
    float es = age / (amax + 1e-6f) + (1.0f - sigf(g_norms[s]));
    unsigned long long pack = ((unsigned long long)__float_as_uint(es) << 32)
                              | (unsigned long long)(0xFFFFFFFFu - (unsigned)s);
    sh[t] = pack; __syncthreads();
    for (int off = 128; off > 0; off >>= 1) {
        if (t < off && sh[t + off] > sh[t]) sh[t] = sh[t + off];
        __syncthreads();
    }
    if (t == 0) atomicMax(&g_s.victim_pack, sh[0]);
}

__global__ void k_fin1() {
    float cap = (float)g_s.n_active / (float)S_SLOTS;
    g_s.capacity = cap;
    g_s.do_erase = (cap > 0.85f) ? 1 : 0;
    float dyn = (cap < 0.3f) ? 0.08f : ((cap < 0.6f) ? 0.08f + (cap - 0.3f) * 0.733f
                                                     : 0.3f + (cap - 0.6f));
    g_s.dyn_thr = fminf(fmaxf(dyn, 0.0f), 0.7f);
    g_s.topk_thr = (cap < 0.3f) ? 0.1f : ((cap < 0.6f) ? 0.2f : 0.4f);
    g_s.raw_thr = (cap < 0.3f) ? 0.3f : 0.5f;
    g_s.victim = (int)(0xFFFFFFFFu - (unsigned)(g_s.victim_pack & 0xFFFFFFFFull));
}

// ---------------- per-b max sim -> novelty ----------------
__global__ void k_maxsim(float* __restrict__ out_nov) {
    int b = blockIdx.x, t = threadIdx.x;
    __shared__ float sh[256];
    float m = -FLT_MAX;
    const float* row = g_sims + (size_t)b * S_SLOTS;
    for (int s = t; s < S_SLOTS; s += 256) m = fmaxf(m, row[s]);
    sh[t] = m; __syncthreads();
    for (int off = 128; off > 0; off >>= 1) {
        if (t < off) sh[t] = fmaxf(sh[t], sh[t + off]);
        __syncthreads();
    }
    if (t == 0) {
        float nov = (1.0f - sh[0]) * 0.5f;
        g_novelty[b] = nov;
        out_nov[b] = nov;
    }
}

__global__ void k_fin2() {
    float s = 0.f;
    for (int b = 0; b < BATCH; b++) s += g_novelty[b];
    g_s.nov_mean = s / (float)BATCH;
}

// ---------------- top-3 of sims2 per b ----------------
__device__ __forceinline__ bool better(float av, int ai, float bv, int bi) {
    return (av > bv) || (av == bv && ai < bi);
}
__global__ void k_top3() {
    int b = blockIdx.x, t = threadIdx.x;
    int de = g_s.do_erase, vic = g_s.victim;
    float v0 = -FLT_MAX, v1 = -FLT_MAX, v2 = -FLT_MAX;
    int i0 = 0x7FFFFFFF, i1 = 0x7FFFFFFF, i2 = 0x7FFFFFFF;
    const float* row = g_sims + (size_t)b * S_SLOTS;
    for (int s = t; s < S_SLOTS; s += 256) {
        float v = row[s];
        if (de && s == vic) v = 0.f;
        if (better(v, s, v2, i2)) {
            if (better(v, s, v1, i1)) {
                if (better(v, s, v0, i0)) { v2=v1;i2=i1; v1=v0;i1=i0; v0=v;i0=s; }
                else                      { v2=v1;i2=i1; v1=v; i1=s; }
            } else                        { v2=v; i2=s; }
        }
    }
    __shared__ float sv[256 * 3];
    __shared__ int   si[256 * 3];
    sv[t*3+0]=v0; sv[t*3+1]=v1; sv[t*3+2]=v2;
    si[t*3+0]=i0; si[t*3+1]=i1; si[t*3+2]=i2;
    __syncthreads();
    if (t == 0) {
        float w0=-FLT_MAX,w1=-FLT_MAX,w2=-FLT_MAX; int j0=0x7FFFFFFF,j1=0x7FFFFFFF,j2=0x7FFFFFFF;
        for (int e = 0; e < 256 * 3; e++) {
            float v = sv[e]; int s = si[e];
            if (better(v, s, w2, j2)) {
                if (better(v, s, w1, j1)) {
                    if (better(v, s, w0, j0)) { w2=w1;j2=j1; w1=w0;j1=j0; w0=v;j0=s; }
                    else                      { w2=w1;j2=j1; w1=v; j1=s; }
                } else                        { w2=v; j2=s; }
            }
        }
        g_tv[b*3+0]=w0; g_tv[b*3+1]=w1; g_tv[b*3+2]=w2;
        g_ti[b*3+0]=j0; g_ti[b*3+1]=j1; g_ti[b*3+2]=j2;
    }
}

// ---------------- perc count ----------------
__global__ void k_perc() {
    int t = threadIdx.x;
    __shared__ int sh[256];
    float nm = g_s.nov_mean;
    int cnt = 0;
    for (size_t i = (size_t)blockIdx.x * 256 + t; i < (size_t)BATCH * S_SLOTS;
         i += (size_t)gridDim.x * 256) {
        int s = (int)(i & (S_SLOTS - 1));
        float v = g_sims[i];
        if ((nm > 1.0f - v) && (g_norms[s] > 0.5f)) cnt++;
    }
    sh[t] = cnt; __syncthreads();
    for (int off = 128; off > 0; off >>= 1) { if (t < off) sh[t] += sh[t + off]; __syncthreads(); }
    if (t == 0) atomicAdd(&g_s.cond_count, sh[0]);
}

// ---------------- store gate path (one block per b) ----------------
__global__ void k_store(const float* __restrict__ nc, const float* __restrict__ q,
                        const float* __restrict__ sr_w1, const float* __restrict__ sr_b1,
                        const float* __restrict__ sr_g,  const float* __restrict__ sr_beta,
                        const float* __restrict__ sr_w2, const float* __restrict__ sr_b2,
                        const float* __restrict__ sn_w,  const float* __restrict__ sn_b,
                        const float* __restrict__ sg_w,  const float* __restrict__ sg_b,
                        float* __restrict__ out_store) {
    int b = blockIdx.x, t = threadIdx.x;   // 256 threads
    __shared__ float comb[1024];
    __shared__ float rh[256];
    __shared__ float red[256];
    for (int i = t; i < 512; i += 256) {
        comb[i] = nc[b * 512 + i];
        comb[512 + i] = q[b * 512 + i];
    }
    __syncthreads();
    float h = sr_b1[t];
    for (int k = 0; k < 1024; k++) h = fmaf(comb[k], sr_w1[k * 256 + t], h);
    // LN
    red[t] = h; __syncthreads();
    for (int off = 128; off > 0; off >>= 1) { if (t < off) red[t] += red[t + off]; __syncthreads(); }
    float m = red[0] / 256.0f; __syncthreads();
    float d = h - m;
    red[t] = d * d; __syncthreads();
    for (int off = 128; off > 0; off >>= 1) { if (t < off) red[t] += red[t + off]; __syncthreads(); }
    float var = red[0] / 256.0f; __syncthreads();
    float hn = d * rsqrtf(var + 1e-5f) * sr_g[t] + sr_beta[t];
    rh[t] = fmaxf(hn, 0.f);
    __syncthreads();
    float val = 0.f;
    if (t < 128) {
        float r = sr_b2[t];
        for (int k = 0; k < 256; k++) r = fmaf(rh[k], sr_w2[k * 128 + t], r);
        r = fmaxf(r, 0.f);
        float nfv = sn_b[t];
        for (int k = 0; k < 512; k++) nfv = fmaf(comb[k], sn_w[k * 128 + t], nfv);
        nfv = sigf(nfv);
        val = (r + nfv) * sg_w[t];
    }
    red[t] = val; __syncthreads();
    for (int off = 128; off > 0; off >>= 1) { if (t < off) red[t] += red[t + off]; __syncthreads(); }
    if (t == 0) {
        float sc = sigf(red[0] + sg_b[0]);
        g_storev[b] = sc;
        out_store[b] = sc;
    }
}

// ---------------- pair MLPs (prob, strength), 8 pairs per block ----------------
__global__ void k_pair(const float* __restrict__ nc, const float* __restrict__ mem,
                       const float* __restrict__ dd_w1, const float* __restrict__ dd_b1,
                       const float* __restrict__ dd_w2, const float* __restrict__ dd_b2,
                       const float* __restrict__ ds_w1, const float* __restrict__ ds_b1,
                       const float* __restrict__ ds_w2, const float* __restrict__ ds_b2) {
    __shared__ float pair[8][1024];
    __shared__ float red[256];
    int t = threadIdx.x;
    int p0 = blockIdx.x * 8;
    int de = g_s.do_erase, vic = g_s.victim;
    for (int p = 0; p < 8; p++) {
        int pi = p0 + p;
        int b = pi / 3;
        int ti = g_ti[pi];
        bool z = (de && ti == vic);
        for (int i = t; i < 512; i += 256) {
            pair[p][i] = nc[b * 512 + i];
            pair[p][512 + i] = z ? 0.f : mem[(size_t)ti * 512 + i];
        }
    }
    __syncthreads();
    float ad[8], as_[8];
#pragma unroll
    for (int p = 0; p < 8; p++) { ad[p] = dd_b1[t]; as_[p] = ds_b1[t]; }
    for (int k = 0; k < 1024; k++) {
        float wd = dd_w1[k * 256 + t];
        float ws = ds_w1[k * 256 + t];
#pragma unroll
        for (int p = 0; p < 8; p++) {
            float x = pair[p][k];
            ad[p]  = fmaf(x, wd, ad[p]);
            as_[p] = fmaf(x, ws, as_[p]);
        }
    }
    float w2d = dd_w2[t], w2s = ds_w2[t];
#pragma unroll
    for (int p = 0; p < 8; p++) {
        ad[p]  = fmaxf(ad[p], 0.f) * w2d;
        as_[p] = fmaxf(as_[p], 0.f) * w2s;
    }
    for (int p = 0; p < 8; p++) {
        red[t] = ad[p]; __syncthreads();
        for (int off = 128; off > 0; off >>= 1) { if (t < off) red[t] += red[t + off]; __syncthreads(); }
        if (t == 0) g_prob[p0 + p] = sigf(red[0] + dd_b2[0]);
        __syncthreads();
        red[t] = as_[p]; __syncthreads();
        for (int off = 128; off > 0; off >>= 1) { if (t < off) red[t] += red[t + off]; __syncthreads(); }
        if (t == 0) g_strength[p0 + p] = sigf(red[0] + ds_b2[0]);
        __syncthreads();
    }
}

// ---------------- erase scores ----------------
__global__ void k_erase1(const float* __restrict__ at,
                         const float* __restrict__ el_w, const float* __restrict__ el_b,
                         const float* __restrict__ ec_b,
                         const float* __restrict__ eg_w, const float* __restrict__ eg_b) {
    int s = blockIdx.x * 256 + threadIdx.x;
    int t = threadIdx.x;
    __shared__ unsigned sh[256];
    int de = g_s.do_erase, vic = g_s.victim;
    float atv = at[s];
    bool zv = (de && s == vic);
    if (zv) atv = -99999.0f;
    float x = (g_s.stepf - atv) * 0.001f;
    float acc = eg_b[0];
    for (int j = 0; j < 32; j++) {
        float lru = fmaxf(fmaf(x, el_w[j], el_b[j]), 0.f);
        float cd = zv ? 0.f : g_confdot[(size_t)s * 32 + j];
        float conf = sigf(cd + ec_b[j]);
        acc += lru * eg_w[j] + conf * eg_w[32 + j];
    }
    float e = sigf(acc);
    g_erase[s] = e;
    float sa = g_s.stepf - atv;
    g_slotage[s] = sa;
    bool recent = (atv >= 0.f) && (sa < 3.f);
    float mp = recent ? 0.f : e;
    g_maskedpre[s] = mp;
    sh[t] = __float_as_uint(mp); __syncthreads();
    for (int off = 128; off > 0; off >>= 1) {
        if (t < off && sh[t + off] > sh[t]) sh[t] = sh[t + off];
        __syncthreads();
    }
    if (t == 0) atomicMax(&g_s.masked_max_bits, sh[0]);
}

// ---------------- finalize decisions + drifted_new[0] ----------------
__global__ void k_fin3(const float* __restrict__ nc, const float* __restrict__ mem) {
    int t = threadIdx.x;  // 512 threads
    if (t == 0) {
        float ssum = 0.f;
        for (int b = 0; b < BATCH; b++) ssum += g_storev[b];
        float smean = ssum / (float)BATCH;
        int na = g_s.n_active;
        int nam = na > 1 ? na : 1;
        float denom = 64.0f * (float)nam;
        float perc = (na > 0) ? ((float)g_s.cond_count / denom) : 1.0f;
        bool base = smean > g_s.raw_thr;
        bool novok = g_s.nov_mean > g_s.dyn_thr;
        bool topok = perc > g_s.topk_thr;
        bool ss = base && novok && topok;
        if (g_s.do_erase && !novok) ss = false;
        g_s.should_store = ss ? 1 : 0;
        g_s.use_slotage = (__uint_as_float(g_s.masked_max_bits) <= 0.0f) ? 1 : 0;
        for (int p = 0; p < BATCH * 3; p++) {
            float tv = g_tv[p];
            g_apply[p] = (tv > 0.7f && tv < 0.99f && g_prob[p] > 0.5f) ? 1 : 0;
        }
    }
    __syncthreads();
    float nc0 = nc[t];
    float v = nc0;
    for (int k = 0; k < 3; k++) {
        if (g_apply[k]) {
            int r = g_ti[k];
            float g = (g_s.do_erase && r == g_s.victim) ? 0.f : mem[(size_t)r * 512 + t];
            float st = g_strength[k];
            float avg = 0.5f * (nc0 + g);
            v = (1.f - st) * nc0 + st * avg;
        }
    }
    g_drifted0[t] = v;
}

// ---------------- argmax of masked_final ----------------
__global__ void k_wmax() {
    int s = blockIdx.x * 256 + threadIdx.x;
    int t = threadIdx.x;
    __shared__ unsigned long long sh[256];
    float mf = g_s.use_slotage ? g_slotage[s] : g_maskedpre[s];
    unsigned long long pack = ((unsigned long long)__float_as_uint(mf) << 32)
                              | (unsigned long long)(0xFFFFFFFFu - (unsigned)s);
    sh[t] = pack; __syncthreads();
    for (int off = 128; off > 0; off >>= 1) {
        if (t < off && sh[t + off] > sh[t]) sh[t] = sh[t + off];
        __syncthreads();
    }
    if (t == 0) atomicMax(&g_s.wmax_pack, sh[0]);
}

__global__ void k_fin4() {
    int wi = g_s.do_erase ? g_s.victim
                          : (int)(0xFFFFFFFFu - (unsigned)(g_s.wmax_pack & 0xFFFFFFFFull));
    g_s.write_idx = wi;
    // changed rows (unique)
    int n = 0;
    if (g_s.do_erase) g_chg[n++] = g_s.victim;
    for (int p = 0; p < BATCH * 3; p++) {
        if (g_apply[p]) {
            int r = g_ti[p];
            int found = 0;
            for (int j = 0; j < n; j++) if (g_chg[j] == r) { found = 1; break; }
            if (!found) g_chg[n++] = r;
        }
    }
    if (g_s.should_store) {
        int r = wi, found = 0;
        for (int j = 0; j < n; j++) if (g_chg[j] == r) { found = 1; break; }
        if (!found) g_chg[n++] = r;
    }
    g_nchg = n;
}

// ---------------- at + erase_out outputs ----------------
__global__ void k_outputs(const float* __restrict__ at,
                          float* __restrict__ out_at, float* __restrict__ out_erase) {
    int s = blockIdx.x * 256 + threadIdx.x;
    float atv = at[s];
    if (g_s.do_erase && s == g_s.victim) atv = -99999.0f;
    if (g_s.should_store && s == g_s.write_idx) atv = g_s.stepf;
    out_at[s] = atv;
    float mf = g_s.use_slotage ? g_slotage[s] : g_maskedpre[s];
    out_erase[s] = (g_s.should_store && !g_s.do_erase) ? mf : g_erase[s];
}

// ---------------- patch out_mem rows ----------------
__global__ void k_patch(const float* __restrict__ nc, const float* __restrict__ mem,
                        float* __restrict__ out_mem) {
    int d = threadIdx.x;  // 512 threads, each owns column d (no races)
    int de = g_s.do_erase, vic = g_s.victim;
    if (de) out_mem[(size_t)vic * 512 + d] = 0.f;
    for (int k = 0; k < 3; k++) {
        for (int b = 0; b < BATCH; b++) {
            int p = b * 3 + k;
            if (g_apply[p]) {
                int r = g_ti[p];
                float g = (de && r == vic) ? 0.f : mem[(size_t)r * 512 + d];
                float st = g_strength[p];
                float ncv = nc[b * 512 + d];
                float avg = 0.5f * (ncv + g);
                out_mem[(size_t)r * 512 + d] = (1.f - st) * g + st * avg;
            }
        }
    }
    if (g_s.should_store) out_mem[(size_t)g_s.write_idx * 512 + d] = g_drifted0[d];
}

// ---------------- recent_changes (sparse) ----------------
__global__ void k_rc(const float* __restrict__ mem, const float* __restrict__ out_mem) {
    int t = threadIdx.x;
    __shared__ float sh[256];
    for (int idx = blockIdx.x; idx < g_nchg; idx += gridDim.x) {
        int r = g_chg[idx];
        float s = 0.f;
        for (int d = t; d < 512; d += 256)
            s += fabsf(out_mem[(size_t)r * 512 + d] - mem[(size_t)r * 512 + d]);
        sh[t] = s; __syncthreads();
        for (int off = 128; off > 0; off >>= 1) { if (t < off) sh[t] += sh[t + off]; __syncthreads(); }
        if (t == 0) g_rowsum[idx] = sh[0];
        __syncthreads();
    }
}

__global__ void k_rcfin(float* __restrict__ out_rc) {
    float s = 0.f;
    int n = g_nchg;
    for (int i = 0; i < n; i++) s += g_rowsum[i];
    out_rc[0] = s / ((float)S_SLOTS * (float)DIM);
}

// ---------------- launch ----------------
extern "C" void kernel_launch(void* const* d_in, const int* in_sizes, int n_in,
                              void* d_out, int out_size) {
    // Input order: setup_inputs-dict order (current_step at idx 4, size 1) or
    // reference-signature order (current_step last). Detect via in_sizes[4].
    bool dictOrder = (in_sizes[4] == 1);
    const float* nc   = (const float*)d_in[0];
    const float* q    = (const float*)d_in[1];
    const float* mem  = (const float*)d_in[2];
    const float* at   = (const float*)d_in[3];
    int base = dictOrder ? 5 : 4;
    const float* sr_w1 = (const float*)d_in[base + 0];
    const float* sr_b1 = (const float*)d_in[base + 1];
    const float* sr_g  = (const float*)d_in[base + 2];
    const float* sr_be = (const float*)d_in[base + 3];
    const float* sr_w2 = (const float*)d_in[base + 4];
    const float* sr_b2 = (const float*)d_in[base + 5];
    const float* sn_w  = (const float*)d_in[base + 6];
    const float* sn_b  = (const float*)d_in[base + 7];
    const float* sg_w  = (const float*)d_in[base + 8];
    const float* sg_b  = (const float*)d_in[base + 9];
    const float* el_w  = (const float*)d_in[base + 10];
    const float* el_b  = (const float*)d_in[base + 11];
    const float* ec_w  = (const float*)d_in[base + 12];
    const float* ec_b  = (const float*)d_in[base + 13];
    const float* eg_w  = (const float*)d_in[base + 14];
    const float* eg_b  = (const float*)d_in[base + 15];
    const float* dd_w1 = (const float*)d_in[base + 16];
    const float* dd_b1 = (const float*)d_in[base + 17];
    const float* dd_w2 = (const float*)d_in[base + 18];
    const float* dd_b2 = (const float*)d_in[base + 19];
    const float* ds_w1 = (const float*)d_in[base + 20];
    const float* ds_b1 = (const float*)d_in[base + 21];
    const float* ds_w2 = (const float*)d_in[base + 22];
    const float* ds_b2 = (const float*)d_in[base + 23];
    const void*  step  = dictOrder ? d_in[4] : d_in[28];

    float* out_mem   = (float*)d_out;
    float* out_at    = out_mem + (size_t)S_SLOTS * DIM;
    float* out_erase = out_at + S_SLOTS;
    float* out_store = out_erase + S_SLOTS;
    float* out_nov   = out_store + BATCH;
    float* out_rc    = out_nov + BATCH;

    k_reset<<<1, 1>>>(step);
    k_normalize<<<BATCH, 128>>>(nc);
    k_main<<<S_SLOTS / 128, 192>>>(mem, ec_w, out_mem);
    k_reduce1<<<S_SLOTS / 256, 256>>>(at);
    k_victim<<<S_SLOTS / 256, 256>>>(at);
    k_fin1<<<1, 1>>>();
    k_maxsim<<<BATCH, 256>>>(out_nov);
    k_fin2<<<1, 1>>>();
    k_top3<<<BATCH, 256>>>();
    k_perc<<<2048, 256>>>();
    k_store<<<BATCH, 256>>>(nc, q, sr_w1, sr_b1, sr_g, sr_be, sr_w2, sr_b2,
                            sn_w, sn_b, sg_w, sg_b, out_store);
    k_pair<<<BATCH * 3 / 8, 256>>>(nc, mem, dd_w1, dd_b1, dd_w2, dd_b2,
                                   ds_w1, ds_b1, ds_w2, ds_b2);
    k_erase1<<<S_SLOTS / 256, 256>>>(at, el_w, el_b, ec_b, eg_w, eg_b);
    k_fin3<<<1, 512>>>(nc, mem);
    k_wmax<<<S_SLOTS / 256, 256>>>();
    k_fin4<<<1, 1>>>();
    k_outputs<<<S_SLOTS / 256, 256>>>(at, out_at, out_erase);
    k_patch<<<1, 512>>>(nc, mem, out_mem);
    k_rc<<<64, 256>>>(mem, out_mem);
    k_rcfin<<<1, 1>>>(out_rc);
}

// round 3
// speedup vs baseline: 1.2139x; 1.2139x over previous
#include <cuda_runtime.h>
#include <math.h>
#include <float.h>

#define S_SLOTS 65536
#define DIM     512
#define BATCH   64

// ---------------- device scratch ----------------
__device__ float g_ncinv[BATCH];
__device__ float g_nnT[DIM * BATCH];                  // transposed normalized new_content [k][b]
__device__ float g_sims[(size_t)BATCH * S_SLOTS];     // [b][s]
__device__ float g_confdot[(size_t)S_SLOTS * 32];     // [s][j]
__device__ float g_norms[S_SLOTS];
__device__ float g_erase[S_SLOTS];
__device__ float g_maskedpre[S_SLOTS];
__device__ float g_slotage[S_SLOTS];
__device__ unsigned g_bmax[BATCH];                    // encoded per-b max sim
__device__ float g_storev[BATCH];
__device__ int   g_ti[BATCH * 3];
__device__ float g_tv[BATCH * 3];
__device__ float g_prob[BATCH * 3];
__device__ float g_strength[BATCH * 3];
__device__ int   g_apply[BATCH * 3];
__device__ float g_drifted0[DIM];
__device__ int   g_chg[256];
__device__ int   g_nchg;

struct Scalars {
    float stepf;
    int   n_active;
    unsigned int age_max_bits;
    unsigned long long victim_pack;
    int   cond_count;
    unsigned int masked_max_bits;
    unsigned long long wpack_m;   // argmax maskedpre
    unsigned long long wpack_a;   // argmax slotage
    int   do_erase;
    int   victim;
    float dyn_thr, topk_thr, raw_thr;
    float nov_mean;
    int   should_store;
    int   use_slotage;
    int   write_idx;
};
__device__ Scalars g_s;

__device__ __forceinline__ float sigf(float x) { return 1.0f / (1.0f + expf(-x)); }
__device__ __forceinline__ unsigned fenc(float f) {
    unsigned u = __float_as_uint(f);
    return (u & 0x80000000u) ? ~u : (u | 0x80000000u);
}
__device__ __forceinline__ float fdec(unsigned u) {
    return (u & 0x80000000u) ? __uint_as_float(u ^ 0x80000000u) : __uint_as_float(~u);
}

// ---------------- 0: reset ----------------
__global__ void k_reset(const void* step_ptr) {
    int t = threadIdx.x;
    if (t == 0) {
        int   iv = *(const int*)step_ptr;
        float fv = *(const float*)step_ptr;
        g_s.stepf = (iv > 0 && iv < 100000000) ? (float)iv : fv;
        g_s.n_active = 0;
        g_s.age_max_bits = 0u;
        g_s.victim_pack = 0ull;
        g_s.cond_count = 0;
        g_s.masked_max_bits = 0u;
        g_s.wpack_m = 0ull;
        g_s.wpack_a = 0ull;
    }
    if (t < BATCH) g_bmax[t] = 0u;
}

// ---------------- 1: nc row inv-norms ----------------
__global__ void k_norm_a(const float* __restrict__ nc) {
    int b = blockIdx.x, t = threadIdx.x;   // 128 threads
    __shared__ float red[128];
    float s = 0.f;
    for (int i = t; i < DIM; i += 128) { float v = nc[b * DIM + i]; s += v * v; }
    red[t] = s; __syncthreads();
    for (int off = 64; off > 0; off >>= 1) { if (t < off) red[t] += red[t + off]; __syncthreads(); }
    if (t == 0) g_ncinv[b] = 1.0f / fmaxf(sqrtf(red[0]), 1e-12f);
}

// ---------------- 2: write transposed normalized nc ----------------
__global__ void k_norm_b(const float* __restrict__ nc) {
    int k = blockIdx.x, b = threadIdx.x;   // 512 blocks x 64 threads
    g_nnT[k * BATCH + b] = nc[b * DIM + k] * g_ncinv[b];
}

// ---------------- 3: store gate path ----------------
__global__ void k_store(const float* __restrict__ nc, const float* __restrict__ q,
                        const float* __restrict__ sr_w1, const float* __restrict__ sr_b1,
                        const float* __restrict__ sr_g,  const float* __restrict__ sr_beta,
                        const float* __restrict__ sr_w2, const float* __restrict__ sr_b2,
                        const float* __restrict__ sn_w,  const float* __restrict__ sn_b,
                        const float* __restrict__ sg_w,  const float* __restrict__ sg_b,
                        float* __restrict__ out_store) {
    int b = blockIdx.x, t = threadIdx.x;   // 256 threads
    __shared__ float comb[1024];
    __shared__ float rh[256];
    __shared__ float red[256];
    for (int i = t; i < 512; i += 256) {
        comb[i] = nc[b * 512 + i];
        comb[512 + i] = q[b * 512 + i];
    }
    __syncthreads();
    float h = sr_b1[t];
    for (int k = 0; k < 1024; k++) h = fmaf(comb[k], sr_w1[k * 256 + t], h);
    red[t] = h; __syncthreads();
    for (int off = 128; off > 0; off >>= 1) { if (t < off) red[t] += red[t + off]; __syncthreads(); }
    float m = red[0] / 256.0f; __syncthreads();
    float d = h - m;
    red[t] = d * d; __syncthreads();
    for (int off = 128; off > 0; off >>= 1) { if (t < off) red[t] += red[t + off]; __syncthreads(); }
    float var = red[0] / 256.0f; __syncthreads();
    float hn = d * rsqrtf(var + 1e-5f) * sr_g[t] + sr_beta[t];
    rh[t] = fmaxf(hn, 0.f);
    __syncthreads();
    float val = 0.f;
    if (t < 128) {
        float r = sr_b2[t];
        for (int k = 0; k < 256; k++) r = fmaf(rh[k], sr_w2[k * 128 + t], r);
        r = fmaxf(r, 0.f);
        float nfv = sn_b[t];
        for (int k = 0; k < 512; k++) nfv = fmaf(comb[k], sn_w[k * 128 + t], nfv);
        nfv = sigf(nfv);
        val = (r + nfv) * sg_w[t];
    }
    red[t] = val; __syncthreads();
    for (int off = 128; off > 0; off >>= 1) { if (t < off) red[t] += red[t + off]; __syncthreads(); }
    if (t == 0) {
        float sc = sigf(red[0] + sg_b[0]);
        g_storev[b] = sc;
        out_store[b] = sc;
    }
}

// ---------------- 4: age max (independent of mem) ----------------
__global__ void k_agemax(const float* __restrict__ at) {
    int s = blockIdx.x * 256 + threadIdx.x;
    int t = threadIdx.x;
    __shared__ unsigned sh[256];
    float age = fmaxf(g_s.stepf - at[s], 0.f);
    sh[t] = __float_as_uint(age);   // nonneg: uint order == float order
    __syncthreads();
    for (int off = 128; off > 0; off >>= 1) {
        if (t < off && sh[t + off] > sh[t]) sh[t] = sh[t + off];
        __syncthreads();
    }
    if (t == 0) atomicMax(&g_s.age_max_bits, sh[0]);
}

// ---------------- 5: fused main GEMM (PROFILED: 6th launch) ----------------
// C[S,96] = mem[S,512] @ [nn^T | ec_w], fused mem->out copy, row norms,
// per-b running max of sims. f32x2 packed FMA, reg-staged double buffering,
// XOR-swizzled A tile (conflict-free STS & LDS).
#define A_IDX(k, r) ((k) * 128 + ((r) ^ ((((k) >> 2) & 7) << 2)))

__global__ void __launch_bounds__(192, 2) k_main(const float* __restrict__ mem,
                                                 const float* __restrict__ ec_w,
                                                 float* __restrict__ out_mem) {
    __shared__ float As[32 * 128];
    __shared__ float Bs[32][100];
    __shared__ float nsh[128];
    const int t  = threadIdx.x;
    const int rg = t & 15;
    const int cg = t >> 4;      // 0..11
    const int row0 = blockIdx.x * 128;

    unsigned long long acc[8][4];
#pragma unroll
    for (int i = 0; i < 8; i++)
#pragma unroll
        for (int j = 0; j < 4; j++) acc[i][j] = 0ull;
    float sq[8] = {0.f,0.f,0.f,0.f,0.f,0.f,0.f,0.f};

    float4 rA[6];
    float4 rB[4];

    // ---- stage chunk 0 (LDG + copy to out) ----
    {
        const int kc = 0;
#pragma unroll
        for (int u = 0; u < 6; u++) {
            int idx = t + 192 * u;
            if (idx < 1024) {
                int r = idx >> 3, f = idx & 7;
                size_t go = (size_t)(row0 + r) * DIM + kc + f * 4;
                float4 v = *(const float4*)(mem + go);
                rA[u] = v;
                *(float4*)(out_mem + go) = v;
            }
        }
#pragma unroll
        for (int u = 0; u < 4; u++) {
            int v = t + 192 * u;
            if (v < 512) { int k = v >> 4, c4 = v & 15; rB[u] = *(const float4*)(g_nnT + (kc + k) * 64 + c4 * 4); }
            else { int w = v - 512; int k = w >> 3, c4 = w & 7; rB[u] = *(const float4*)(ec_w + (size_t)(kc + k) * 32 + c4 * 4); }
        }
    }

    for (int kc = 0; kc < DIM; kc += 32) {
        __syncthreads();
        // STS staged tile
#pragma unroll
        for (int u = 0; u < 6; u++) {
            int idx = t + 192 * u;
            if (idx < 1024) {
                int r = idx >> 3, f = idx & 7;
                As[A_IDX(f * 4 + 0, r)] = rA[u].x;
                As[A_IDX(f * 4 + 1, r)] = rA[u].y;
                As[A_IDX(f * 4 + 2, r)] = rA[u].z;
                As[A_IDX(f * 4 + 3, r)] = rA[u].w;
            }
        }
#pragma unroll
        for (int u = 0; u < 4; u++) {
            int v = t + 192 * u;
            if (v < 512) { int k = v >> 4, c4 = v & 15; *(float4*)(&Bs[k][c4 * 4]) = rB[u]; }
            else { int w = v - 512; int k = w >> 3, c4 = w & 7; *(float4*)(&Bs[k][64 + c4 * 4]) = rB[u]; }
        }
        __syncthreads();
        // stage next chunk
        if (kc + 32 < DIM) {
            const int kn = kc + 32;
#pragma unroll
            for (int u = 0; u < 6; u++) {
                int idx = t + 192 * u;
                if (idx < 1024) {
                    int r = idx >> 3, f = idx & 7;
                    size_t go = (size_t)(row0 + r) * DIM + kn + f * 4;
                    float4 v = *(const float4*)(mem + go);
                    rA[u] = v;
                    *(float4*)(out_mem + go) = v;
                }
            }
#pragma unroll
            for (int u = 0; u < 4; u++) {
                int v = t + 192 * u;
                if (v < 512) { int k = v >> 4, c4 = v & 15; rB[u] = *(const float4*)(g_nnT + (kn + k) * 64 + c4 * 4); }
                else { int w = v - 512; int k = w >> 3, c4 = w & 7; rB[u] = *(const float4*)(ec_w + (size_t)(kn + k) * 32 + c4 * 4); }
            }
        }
        // compute
#pragma unroll
        for (int kk = 0; kk < 32; kk++) {
            float a[8];
            unsigned long long a2[8], b2[4];
#pragma unroll
            for (int i = 0; i < 8; i++) {
                a[i] = As[A_IDX(kk, rg + i * 16)];
                unsigned ai = __float_as_uint(a[i]);
                asm("mov.b64 %0, {%1, %2};" : "=l"(a2[i]) : "r"(ai), "r"(ai));
            }
#pragma unroll
            for (int j = 0; j < 4; j++)
                b2[j] = *(const unsigned long long*)(&Bs[kk][cg * 8 + 2 * j]);
#pragma unroll
            for (int i = 0; i < 8; i++)
#pragma unroll
                for (int j = 0; j < 4; j++)
                    asm("fma.rn.f32x2 %0, %1, %2, %0;" : "+l"(acc[i][j]) : "l"(a2[i]), "l"(b2[j]));
            if (cg == 0) {
#pragma unroll
                for (int i = 0; i < 8; i++) sq[i] = fmaf(a[i], a[i], sq[i]);
            }
        }
    }

    if (cg == 0) {
#pragma unroll
        for (int i = 0; i < 8; i++) {
            int r = rg + i * 16;
            float n = sqrtf(sq[i]);
            nsh[r] = n;
            g_norms[row0 + r] = n;
        }
    }
    __syncthreads();

    float mloc[8];
#pragma unroll
    for (int j = 0; j < 8; j++) mloc[j] = -FLT_MAX;

    if (cg < 8) {
        // sims columns
#pragma unroll
        for (int i = 0; i < 8; i++) {
            int r = rg + i * 16;
            int s = row0 + r;
            float inv = 1.0f / fmaxf(nsh[r], 1e-12f);
#pragma unroll
            for (int jp = 0; jp < 4; jp++) {
                float2 f2 = *reinterpret_cast<float2*>(&acc[i][jp]);
                int c0 = cg * 8 + 2 * jp;
                float s0 = f2.x * inv, s1 = f2.y * inv;
                g_sims[(size_t)c0 * S_SLOTS + s] = s0;
                g_sims[(size_t)(c0 + 1) * S_SLOTS + s] = s1;
                mloc[2 * jp]     = fmaxf(mloc[2 * jp], s0);
                mloc[2 * jp + 1] = fmaxf(mloc[2 * jp + 1], s1);
            }
        }
#pragma unroll
        for (int jj = 0; jj < 8; jj++) {
            float m = mloc[jj];
#pragma unroll
            for (int off = 8; off >= 1; off >>= 1)
                m = fmaxf(m, __shfl_xor_sync(0xFFFFFFFFu, m, off));
            if (rg == 0) atomicMax(&g_bmax[cg * 8 + jj], fenc(m));
        }
    } else {
        // confdot columns: 8 consecutive c per thread -> two float4 stores
#pragma unroll
        for (int i = 0; i < 8; i++) {
            int r = rg + i * 16;
            int s = row0 + r;
            float2 p0 = *reinterpret_cast<float2*>(&acc[i][0]);
            float2 p1 = *reinterpret_cast<float2*>(&acc[i][1]);
            float2 p2 = *reinterpret_cast<float2*>(&acc[i][2]);
            float2 p3 = *reinterpret_cast<float2*>(&acc[i][3]);
            float4 q0 = make_float4(p0.x, p0.y, p1.x, p1.y);
            float4 q1 = make_float4(p2.x, p2.y, p3.x, p3.y);
            float* base = g_confdot + (size_t)s * 32 + (cg - 8) * 8;
            *(float4*)(base) = q0;
            *(float4*)(base + 4) = q1;
        }
    }
}

// ---------------- 6: n_active + victim (needs norms + age_max) ----------------
__global__ void k_act_vic(const float* __restrict__ at) {
    int s = blockIdx.x * 256 + threadIdx.x;
    int t = threadIdx.x;
    __shared__ int shi[256];
    __shared__ unsigned long long sh[256];
    float nrm = g_norms[s];
    shi[t] = (nrm > 0.5f) ? 1 : 0;
    float amax = __uint_as_float(g_s.age_max_bits);
    float age = fmaxf(g_s.stepf - at[s], 0.f);
    float es = age / (amax + 1e-6f) + (1.0f - sigf(nrm));
    sh[t] = ((unsigned long long)fenc(es) << 32) | (unsigned long long)(0xFFFFFFFFu - (unsigned)s);
    __syncthreads();
    for (int off = 128; off > 0; off >>= 1) {
        if (t < off) {
            shi[t] += shi[t + off];
            if (sh[t + off] > sh[t]) sh[t] = sh[t + off];
        }
        __syncthreads();
    }
    if (t == 0) {
        atomicAdd(&g_s.n_active, shi[0]);
        atomicMax(&g_s.victim_pack, sh[0]);
    }
}

// ---------------- 7: scalars + novelty ----------------
__global__ void k_fin1(float* __restrict__ out_nov) {
    int t = threadIdx.x;   // 64 threads
    __shared__ float red[64];
    float nov = (1.0f - fdec(g_bmax[t])) * 0.5f;
    out_nov[t] = nov;
    red[t] = nov; __syncthreads();
    for (int off = 32; off > 0; off >>= 1) { if (t < off) red[t] += red[t + off]; __syncthreads(); }
    if (t == 0) {
        g_s.nov_mean = red[0] / (float)BATCH;
        float cap = (float)g_s.n_active / (float)S_SLOTS;
        g_s.do_erase = (cap > 0.85f) ? 1 : 0;
        float dyn = (cap < 0.3f) ? 0.08f : ((cap < 0.6f) ? 0.08f + (cap - 0.3f) * 0.733f
                                                         : 0.3f + (cap - 0.6f));
        g_s.dyn_thr = fminf(fmaxf(dyn, 0.0f), 0.7f);
        g_s.topk_thr = (cap < 0.3f) ? 0.1f : ((cap < 0.6f) ? 0.2f : 0.4f);
        g_s.raw_thr = (cap < 0.3f) ? 0.3f : 0.5f;
        g_s.victim = (int)(0xFFFFFFFFu - (unsigned)(g_s.victim_pack & 0xFFFFFFFFull));
    }
}

// ---------------- 8: fused top3 + perc scan over sims ----------------
__device__ __forceinline__ bool better(float av, int ai, float bv, int bi) {
    return (av > bv) || (av == bv && ai < bi);
}
__global__ void k_scan() {
    int b = blockIdx.x, t = threadIdx.x;
    int de = g_s.do_erase, vic = g_s.victim;
    float nm = g_s.nov_mean;
    float v0 = -FLT_MAX, v1 = -FLT_MAX, v2 = -FLT_MAX;
    int i0 = 0x7FFFFFFF, i1 = 0x7FFFFFFF, i2 = 0x7FFFFFFF;
    int cnt = 0;
    const float* row = g_sims + (size_t)b * S_SLOTS;
    for (int s = t; s < S_SLOTS; s += 256) {
        float vraw = row[s];
        if ((nm > 1.0f - vraw) && (g_norms[s] > 0.5f)) cnt++;
        float v = (de && s == vic) ? 0.f : vraw;
        if (better(v, s, v2, i2)) {
            if (better(v, s, v1, i1)) {
                if (better(v, s, v0, i0)) { v2=v1;i2=i1; v1=v0;i1=i0; v0=v;i0=s; }
                else                      { v2=v1;i2=i1; v1=v; i1=s; }
            } else                        { v2=v; i2=s; }
        }
    }
    __shared__ float sv[256 * 3];
    __shared__ int   si[256 * 3];
    __shared__ int   sc[256];
    sv[t*3+0]=v0; sv[t*3+1]=v1; sv[t*3+2]=v2;
    si[t*3+0]=i0; si[t*3+1]=i1; si[t*3+2]=i2;
    sc[t] = cnt;
    __syncthreads();
    for (int off = 128; off > 0; off >>= 1) { if (t < off) sc[t] += sc[t + off]; __syncthreads(); }
    if (t == 0) {
        atomicAdd(&g_s.cond_count, sc[0]);
        float w0=-FLT_MAX,w1=-FLT_MAX,w2=-FLT_MAX; int j0=0x7FFFFFFF,j1=0x7FFFFFFF,j2=0x7FFFFFFF;
        for (int e = 0; e < 256 * 3; e++) {
            float v = sv[e]; int s = si[e];
            if (better(v, s, w2, j2)) {
                if (better(v, s, w1, j1)) {
                    if (better(v, s, w0, j0)) { w2=w1;j2=j1; w1=w0;j1=j0; w0=v;j0=s; }
                    else                      { w2=w1;j2=j1; w1=v; j1=s; }
                } else                        { w2=v; j2=s; }
            }
        }
        g_tv[b*3+0]=w0; g_tv[b*3+1]=w1; g_tv[b*3+2]=w2;
        g_ti[b*3+0]=j0; g_ti[b*3+1]=j1; g_ti[b*3+2]=j2;
    }
}

// ---------------- 9: pair MLPs, 4 pairs/block x 48 blocks ----------------
__global__ void k_pair(const float* __restrict__ nc, const float* __restrict__ mem,
                       const float* __restrict__ dd_w1, const float* __restrict__ dd_b1,
                       const float* __restrict__ dd_w2, const float* __restrict__ dd_b2,
                       const float* __restrict__ ds_w1, const float* __restrict__ ds_b1,
                       const float* __restrict__ ds_w2, const float* __restrict__ ds_b2) {
    __shared__ float pair[4][1024];
    __shared__ float red[256];
    int t = threadIdx.x;
    int p0 = blockIdx.x * 4;
    int de = g_s.do_erase, vic = g_s.victim;
    for (int p = 0; p < 4; p++) {
        int pi = p0 + p;
        int b = pi / 3;
        int ti = g_ti[pi];
        bool z = (de && ti == vic);
        for (int i = t; i < 512; i += 256) {
            pair[p][i] = nc[b * 512 + i];
            pair[p][512 + i] = z ? 0.f : mem[(size_t)ti * 512 + i];
        }
    }
    __syncthreads();
    float ad[4], as_[4];
#pragma unroll
    for (int p = 0; p < 4; p++) { ad[p] = dd_b1[t]; as_[p] = ds_b1[t]; }
    for (int k = 0; k < 1024; k++) {
        float wd = dd_w1[k * 256 + t];
        float ws = ds_w1[k * 256 + t];
#pragma unroll
        for (int p = 0; p < 4; p++) {
            float x = pair[p][k];
            ad[p]  = fmaf(x, wd, ad[p]);
            as_[p] = fmaf(x, ws, as_[p]);
        }
    }
    float w2d = dd_w2[t], w2s = ds_w2[t];
#pragma unroll
    for (int p = 0; p < 4; p++) {
        ad[p]  = fmaxf(ad[p], 0.f) * w2d;
        as_[p] = fmaxf(as_[p], 0.f) * w2s;
    }
    for (int p = 0; p < 4; p++) {
        red[t] = ad[p]; __syncthreads();
        for (int off = 128; off > 0; off >>= 1) { if (t < off) red[t] += red[t + off]; __syncthreads(); }
        if (t == 0) g_prob[p0 + p] = sigf(red[0] + dd_b2[0]);
        __syncthreads();
        red[t] = as_[p]; __syncthreads();
        for (int off = 128; off > 0; off >>= 1) { if (t < off) red[t] += red[t + off]; __syncthreads(); }
        if (t == 0) g_strength[p0 + p] = sigf(red[0] + ds_b2[0]);
        __syncthreads();
    }
}

// ---------------- 10: erase scores + masked max + dual argmax ----------------
__global__ void k_erase1(const float* __restrict__ at,
                         const float* __restrict__ el_w, const float* __restrict__ el_b,
                         const float* __restrict__ ec_b,
                         const float* __restrict__ eg_w, const float* __restrict__ eg_b) {
    int s = blockIdx.x * 256 + threadIdx.x;
    int t = threadIdx.x;
    __shared__ unsigned shm[256];
    __shared__ unsigned long long pm[256];
    __shared__ unsigned long long pa[256];
    int de = g_s.do_erase, vic = g_s.victim;
    float atv = at[s];
    bool zv = (de && s == vic);
    if (zv) atv = -99999.0f;
    float x = (g_s.stepf - atv) * 0.001f;
    float acc = eg_b[0];
    for (int j = 0; j < 32; j++) {
        float lru = fmaxf(fmaf(x, el_w[j], el_b[j]), 0.f);
        float cd = zv ? 0.f : g_confdot[(size_t)s * 32 + j];
        float conf = sigf(cd + ec_b[j]);
        acc += lru * eg_w[j] + conf * eg_w[32 + j];
    }
    float e = sigf(acc);
    g_erase[s] = e;
    float sa = g_s.stepf - atv;
    g_slotage[s] = sa;
    bool recent = (atv >= 0.f) && (sa < 3.f);
    float mp = recent ? 0.f : e;
    g_maskedpre[s] = mp;
    unsigned idxe = 0xFFFFFFFFu - (unsigned)s;
    shm[t] = __float_as_uint(mp);
    pm[t] = ((unsigned long long)fenc(mp) << 32) | (unsigned long long)idxe;
    pa[t] = ((unsigned long long)fenc(sa) << 32) | (unsigned long long)idxe;
    __syncthreads();
    for (int off = 128; off > 0; off >>= 1) {
        if (t < off) {
            if (shm[t + off] > shm[t]) shm[t] = shm[t + off];
            if (pm[t + off] > pm[t]) pm[t] = pm[t + off];
            if (pa[t + off] > pa[t]) pa[t] = pa[t + off];
        }
        __syncthreads();
    }
    if (t == 0) {
        atomicMax(&g_s.masked_max_bits, shm[0]);
        atomicMax(&g_s.wpack_m, pm[0]);
        atomicMax(&g_s.wpack_a, pa[0]);
    }
}

// ---------------- 11: finalize decisions + drift + patch rows ----------------
__global__ void k_finalize(const float* __restrict__ nc, const float* __restrict__ mem,
                           float* __restrict__ out_mem) {
    int t = threadIdx.x;  // 512 threads
    if (t == 0) {
        float ssum = 0.f;
        for (int b = 0; b < BATCH; b++) ssum += g_storev[b];
        float smean = ssum / (float)BATCH;
        int na = g_s.n_active;
        int nam = na > 1 ? na : 1;
        float perc = (na > 0) ? ((float)g_s.cond_count / (64.0f * (float)nam)) : 1.0f;
        bool base = smean > g_s.raw_thr;
        bool novok = g_s.nov_mean > g_s.dyn_thr;
        bool topok = perc > g_s.topk_thr;
        bool ss = base && novok && topok;
        if (g_s.do_erase && !novok) ss = false;
        g_s.should_store = ss ? 1 : 0;
        int usa = (__uint_as_float(g_s.masked_max_bits) <= 0.0f) ? 1 : 0;
        g_s.use_slotage = usa;
        unsigned long long wp = usa ? g_s.wpack_a : g_s.wpack_m;
        int wmax = (int)(0xFFFFFFFFu - (unsigned)(wp & 0xFFFFFFFFull));
        int wi = g_s.do_erase ? g_s.victim : wmax;
        g_s.write_idx = wi;
        for (int p = 0; p < BATCH * 3; p++) {
            float tv = g_tv[p];
            g_apply[p] = (tv > 0.7f && tv < 0.99f && g_prob[p] > 0.5f) ? 1 : 0;
        }
        // changed-row list
        int n = 0;
        if (g_s.do_erase) g_chg[n++] = g_s.victim;
        for (int p = 0; p < BATCH * 3; p++) {
            if (g_apply[p]) {
                int r = g_ti[p];
                int found = 0;
                for (int j = 0; j < n; j++) if (g_chg[j] == r) { found = 1; break; }
                if (!found) g_chg[n++] = r;
            }
        }
        if (ss) {
            int r = wi, found = 0;
            for (int j = 0; j < n; j++) if (g_chg[j] == r) { found = 1; break; }
            if (!found) g_chg[n++] = r;
        }
        g_nchg = n;
    }
    __syncthreads();
    int de = g_s.do_erase, vic = g_s.victim;
    // drifted_new[0]
    float nc0 = nc[t];
    float v = nc0;
    for (int k = 0; k < 3; k++) {
        if (g_apply[k]) {
            int r = g_ti[k];
            float g = (de && r == vic) ? 0.f : mem[(size_t)r * 512 + t];
            float st = g_strength[k];
            float avg = 0.5f * (nc0 + g);
            v = (1.f - st) * nc0 + st * avg;
        }
    }
    g_drifted0[t] = v;
    // patch out_mem rows (column-owner per thread -> no races)
    if (de) out_mem[(size_t)vic * 512 + t] = 0.f;
    for (int k = 0; k < 3; k++) {
        for (int b = 0; b < BATCH; b++) {
            int p = b * 3 + k;
            if (g_apply[p]) {
                int r = g_ti[p];
                float g = (de && r == vic) ? 0.f : mem[(size_t)r * 512 + t];
                float st = g_strength[p];
                float ncv = nc[b * 512 + t];
                float avg = 0.5f * (ncv + g);
                out_mem[(size_t)r * 512 + t] = (1.f - st) * g + st * avg;
            }
        }
    }
    if (g_s.should_store) out_mem[(size_t)g_s.write_idx * 512 + t] = v * 0.f + g_drifted0[t];
}

// ---------------- 12: at + erase outputs ----------------
__global__ void k_outputs(const float* __restrict__ at,
                          float* __restrict__ out_at, float* __restrict__ out_erase) {
    int s = blockIdx.x * 256 + threadIdx.x;
    float atv = at[s];
    if (g_s.do_erase && s == g_s.victim) atv = -99999.0f;
    if (g_s.should_store && s == g_s.write_idx) atv = g_s.stepf;
    out_at[s] = atv;
    float mf = g_s.use_slotage ? g_slotage[s] : g_maskedpre[s];
    out_erase[s] = (g_s.should_store && !g_s.do_erase) ? mf : g_erase[s];
}

// ---------------- 13: recent_changes (sparse, single block) ----------------
__global__ void k_rc(const float* __restrict__ mem, const float* __restrict__ out_mem,
                     float* __restrict__ out_rc) {
    int t = threadIdx.x;  // 256
    __shared__ float sh[256];
    int n = g_nchg;
    float s = 0.f;
    for (int j = t; j < n * 512; j += 256) {
        int r = g_chg[j >> 9];
        int d = j & 511;
        s += fabsf(out_mem[(size_t)r * 512 + d] - mem[(size_t)r * 512 + d]);
    }
    sh[t] = s; __syncthreads();
    for (int off = 128; off > 0; off >>= 1) { if (t < off) sh[t] += sh[t + off]; __syncthreads(); }
    if (t == 0) out_rc[0] = sh[0] / ((float)S_SLOTS * (float)DIM);
}

// ---------------- launch ----------------
extern "C" void kernel_launch(void* const* d_in, const int* in_sizes, int n_in,
                              void* d_out, int out_size) {
    bool dictOrder = (in_sizes[4] == 1);
    const float* nc   = (const float*)d_in[0];
    const float* q    = (const float*)d_in[1];
    const float* mem  = (const float*)d_in[2];
    const float* at   = (const float*)d_in[3];
    int base = dictOrder ? 5 : 4;
    const float* sr_w1 = (const float*)d_in[base + 0];
    const float* sr_b1 = (const float*)d_in[base + 1];
    const float* sr_g  = (const float*)d_in[base + 2];
    const float* sr_be = (const float*)d_in[base + 3];
    const float* sr_w2 = (const float*)d_in[base + 4];
    const float* sr_b2 = (const float*)d_in[base + 5];
    const float* sn_w  = (const float*)d_in[base + 6];
    const float* sn_b  = (const float*)d_in[base + 7];
    const float* sg_w  = (const float*)d_in[base + 8];
    const float* sg_b  = (const float*)d_in[base + 9];
    const float* el_w  = (const float*)d_in[base + 10];
    const float* el_b  = (const float*)d_in[base + 11];
    const float* ec_w  = (const float*)d_in[base + 12];
    const float* ec_b  = (const float*)d_in[base + 13];
    const float* eg_w  = (const float*)d_in[base + 14];
    const float* eg_b  = (const float*)d_in[base + 15];
    const float* dd_w1 = (const float*)d_in[base + 16];
    const float* dd_b1 = (const float*)d_in[base + 17];
    const float* dd_w2 = (const float*)d_in[base + 18];
    const float* dd_b2 = (const float*)d_in[base + 19];
    const float* ds_w1 = (const float*)d_in[base + 20];
    const float* ds_b1 = (const float*)d_in[base + 21];
    const float* ds_w2 = (const float*)d_in[base + 22];
    const float* ds_b2 = (const float*)d_in[base + 23];
    const void*  step  = dictOrder ? d_in[4] : d_in[28];

    float* out_mem   = (float*)d_out;
    float* out_at    = out_mem + (size_t)S_SLOTS * DIM;
    float* out_erase = out_at + S_SLOTS;
    float* out_store = out_erase + S_SLOTS;
    float* out_nov   = out_store + BATCH;
    float* out_rc    = out_nov + BATCH;

    k_reset<<<1, 64>>>(step);                                   // 1
    k_norm_a<<<BATCH, 128>>>(nc);                               // 2
    k_norm_b<<<DIM, BATCH>>>(nc);                               // 3
    k_store<<<BATCH, 256>>>(nc, q, sr_w1, sr_b1, sr_g, sr_be,   // 4
                            sr_w2, sr_b2, sn_w, sn_b, sg_w, sg_b, out_store);
    k_agemax<<<S_SLOTS / 256, 256>>>(at);                       // 5
    k_main<<<S_SLOTS / 128, 192>>>(mem, ec_w, out_mem);         // 6  <- ncu -s 5 profiles this
    k_act_vic<<<S_SLOTS / 256, 256>>>(at);                      // 7
    k_fin1<<<1, 64>>>(out_nov);                                 // 8
    k_scan<<<BATCH, 256>>>();                                   // 9
    k_pair<<<BATCH * 3 / 4, 256>>>(nc, mem, dd_w1, dd_b1, dd_w2, dd_b2,
                                   ds_w1, ds_b1, ds_w2, ds_b2); // 10
    k_erase1<<<S_SLOTS / 256, 256>>>(at, el_w, el_b, ec_b, eg_w, eg_b); // 11
    k_finalize<<<1, 512>>>(nc, mem, out_mem);                   // 12
    k_outputs<<<S_SLOTS / 256, 256>>>(at, out_at, out_erase);   // 13
    k_rc<<<1, 256>>>(mem, out_mem, out_rc);                     // 14
}

// round 4
// speedup vs baseline: 1.8992x; 1.5646x over previous
#include <cuda_runtime.h>
#include <math.h>
#include <float.h>

#define S_SLOTS 65536
#define DIM     512
#define BATCH   64

// ---------------- device scratch ----------------
__device__ float g_ncinv[BATCH];
__device__ float g_nnT[DIM * BATCH];                  // transposed normalized new_content [k][b]
__device__ float g_sims[(size_t)BATCH * S_SLOTS];     // [b][s]
__device__ float g_confdot[(size_t)S_SLOTS * 32];     // [s][j]
__device__ float g_norms[S_SLOTS];
__device__ float g_erase[S_SLOTS];
__device__ float g_maskedpre[S_SLOTS];
__device__ float g_slotage[S_SLOTS];
__device__ unsigned g_bmax[BATCH];                    // encoded per-b max sim
__device__ float g_storev[BATCH];
__device__ int   g_ti[BATCH * 3];
__device__ float g_tv[BATCH * 3];
__device__ float g_p3v[BATCH * 4 * 3];
__device__ int   g_p3i[BATCH * 4 * 3];
__device__ float g_pairacc[BATCH * 3 * 2];            // partial sums for (pair, net)
__device__ float g_strength[BATCH * 3];
__device__ int   g_apply[BATCH * 3];
__device__ float g_drifted0[DIM];
__device__ int   g_chg[256];
__device__ int   g_nchg;

struct Scalars {
    float stepf;
    int   n_active;
    unsigned int age_max_bits;
    unsigned long long victim_pack;
    int   cond_count;
    unsigned int masked_max_bits;
    unsigned long long wpack_m;   // argmax maskedpre
    unsigned long long wpack_a;   // argmax slotage
    int   do_erase;
    int   victim;
    float dyn_thr, topk_thr, raw_thr;
    float nov_mean;
    int   should_store;
    int   use_slotage;
    int   write_idx;
};
__device__ Scalars g_s;

__device__ __forceinline__ float sigf(float x) { return 1.0f / (1.0f + expf(-x)); }
__device__ __forceinline__ unsigned fenc(float f) {
    unsigned u = __float_as_uint(f);
    return (u & 0x80000000u) ? ~u : (u | 0x80000000u);
}
__device__ __forceinline__ float fdec(unsigned u) {
    return (u & 0x80000000u) ? __uint_as_float(u ^ 0x80000000u) : __uint_as_float(~u);
}

// ---------------- 1: reset ----------------
__global__ void k_reset(const void* step_ptr) {
    int t = threadIdx.x;   // 384
    if (t == 0) {
        int   iv = *(const int*)step_ptr;
        float fv = *(const float*)step_ptr;
        g_s.stepf = (iv > 0 && iv < 100000000) ? (float)iv : fv;
        g_s.n_active = 0;
        g_s.age_max_bits = 0u;
        g_s.victim_pack = 0ull;
        g_s.cond_count = 0;
        g_s.masked_max_bits = 0u;
        g_s.wpack_m = 0ull;
        g_s.wpack_a = 0ull;
    }
    if (t < BATCH) g_bmax[t] = 0u;
    if (t < BATCH * 3 * 2) g_pairacc[t] = 0.f;
}

// ---------------- 2: nc row inv-norms ----------------
__global__ void k_norm_a(const float* __restrict__ nc) {
    int b = blockIdx.x, t = threadIdx.x;   // 128 threads
    __shared__ float red[128];
    float s = 0.f;
    for (int i = t; i < DIM; i += 128) { float v = nc[b * DIM + i]; s += v * v; }
    red[t] = s; __syncthreads();
    for (int off = 64; off > 0; off >>= 1) { if (t < off) red[t] += red[t + off]; __syncthreads(); }
    if (t == 0) g_ncinv[b] = 1.0f / fmaxf(sqrtf(red[0]), 1e-12f);
}

// ---------------- 3: write transposed normalized nc ----------------
__global__ void k_norm_b(const float* __restrict__ nc) {
    int k = blockIdx.x, b = threadIdx.x;   // 512 blocks x 64 threads
    g_nnT[k * BATCH + b] = nc[b * DIM + k] * g_ncinv[b];
}

// ---------------- 4: fused main GEMM (ncu captures this slot) ----------------
#define A_IDX(k, r) ((k) * 128 + ((r) ^ ((((k) >> 2) & 7) << 2)))

__global__ void __launch_bounds__(192, 2) k_main(const float* __restrict__ mem,
                                                 const float* __restrict__ ec_w,
                                                 float* __restrict__ out_mem) {
    __shared__ float As[32 * 128];
    __shared__ float Bs[32][100];
    __shared__ float nsh[128];
    const int t  = threadIdx.x;
    const int rg = t & 15;
    const int cg = t >> 4;      // 0..11
    const int row0 = blockIdx.x * 128;

    unsigned long long acc[8][4];
#pragma unroll
    for (int i = 0; i < 8; i++)
#pragma unroll
        for (int j = 0; j < 4; j++) acc[i][j] = 0ull;
    float sq[8] = {0.f,0.f,0.f,0.f,0.f,0.f,0.f,0.f};

    float4 rA[6];
    float4 rB[4];

    {
        const int kc = 0;
#pragma unroll
        for (int u = 0; u < 6; u++) {
            int idx = t + 192 * u;
            if (idx < 1024) {
                int r = idx >> 3, f = idx & 7;
                size_t go = (size_t)(row0 + r) * DIM + kc + f * 4;
                float4 v = *(const float4*)(mem + go);
                rA[u] = v;
                *(float4*)(out_mem + go) = v;
            }
        }
#pragma unroll
        for (int u = 0; u < 4; u++) {
            int v = t + 192 * u;
            if (v < 512) { int k = v >> 4, c4 = v & 15; rB[u] = *(const float4*)(g_nnT + (kc + k) * 64 + c4 * 4); }
            else { int w = v - 512; int k = w >> 3, c4 = w & 7; rB[u] = *(const float4*)(ec_w + (size_t)(kc + k) * 32 + c4 * 4); }
        }
    }

    for (int kc = 0; kc < DIM; kc += 32) {
        __syncthreads();
#pragma unroll
        for (int u = 0; u < 6; u++) {
            int idx = t + 192 * u;
            if (idx < 1024) {
                int r = idx >> 3, f = idx & 7;
                As[A_IDX(f * 4 + 0, r)] = rA[u].x;
                As[A_IDX(f * 4 + 1, r)] = rA[u].y;
                As[A_IDX(f * 4 + 2, r)] = rA[u].z;
                As[A_IDX(f * 4 + 3, r)] = rA[u].w;
            }
        }
#pragma unroll
        for (int u = 0; u < 4; u++) {
            int v = t + 192 * u;
            if (v < 512) { int k = v >> 4, c4 = v & 15; *(float4*)(&Bs[k][c4 * 4]) = rB[u]; }
            else { int w = v - 512; int k = w >> 3, c4 = w & 7; *(float4*)(&Bs[k][64 + c4 * 4]) = rB[u]; }
        }
        __syncthreads();
        if (kc + 32 < DIM) {
            const int kn = kc + 32;
#pragma unroll
            for (int u = 0; u < 6; u++) {
                int idx = t + 192 * u;
                if (idx < 1024) {
                    int r = idx >> 3, f = idx & 7;
                    size_t go = (size_t)(row0 + r) * DIM + kn + f * 4;
                    float4 v = *(const float4*)(mem + go);
                    rA[u] = v;
                    *(float4*)(out_mem + go) = v;
                }
            }
#pragma unroll
            for (int u = 0; u < 4; u++) {
                int v = t + 192 * u;
                if (v < 512) { int k = v >> 4, c4 = v & 15; rB[u] = *(const float4*)(g_nnT + (kn + k) * 64 + c4 * 4); }
                else { int w = v - 512; int k = w >> 3, c4 = w & 7; rB[u] = *(const float4*)(ec_w + (size_t)(kn + k) * 32 + c4 * 4); }
            }
        }
#pragma unroll
        for (int kk = 0; kk < 32; kk++) {
            float a[8];
            unsigned long long a2[8], b2[4];
#pragma unroll
            for (int i = 0; i < 8; i++) {
                a[i] = As[A_IDX(kk, rg + i * 16)];
                unsigned ai = __float_as_uint(a[i]);
                asm("mov.b64 %0, {%1, %2};" : "=l"(a2[i]) : "r"(ai), "r"(ai));
            }
#pragma unroll
            for (int j = 0; j < 4; j++)
                b2[j] = *(const unsigned long long*)(&Bs[kk][cg * 8 + 2 * j]);
#pragma unroll
            for (int i = 0; i < 8; i++)
#pragma unroll
                for (int j = 0; j < 4; j++)
                    asm("fma.rn.f32x2 %0, %1, %2, %0;" : "+l"(acc[i][j]) : "l"(a2[i]), "l"(b2[j]));
            if (cg == 0) {
#pragma unroll
                for (int i = 0; i < 8; i++) sq[i] = fmaf(a[i], a[i], sq[i]);
            }
        }
    }

    if (cg == 0) {
#pragma unroll
        for (int i = 0; i < 8; i++) {
            int r = rg + i * 16;
            float n = sqrtf(sq[i]);
            nsh[r] = n;
            g_norms[row0 + r] = n;
        }
    }
    __syncthreads();

    float mloc[8];
#pragma unroll
    for (int j = 0; j < 8; j++) mloc[j] = -FLT_MAX;

    if (cg < 8) {
#pragma unroll
        for (int i = 0; i < 8; i++) {
            int r = rg + i * 16;
            int s = row0 + r;
            float inv = 1.0f / fmaxf(nsh[r], 1e-12f);
#pragma unroll
            for (int jp = 0; jp < 4; jp++) {
                float2 f2 = *reinterpret_cast<float2*>(&acc[i][jp]);
                int c0 = cg * 8 + 2 * jp;
                float s0 = f2.x * inv, s1 = f2.y * inv;
                g_sims[(size_t)c0 * S_SLOTS + s] = s0;
                g_sims[(size_t)(c0 + 1) * S_SLOTS + s] = s1;
                mloc[2 * jp]     = fmaxf(mloc[2 * jp], s0);
                mloc[2 * jp + 1] = fmaxf(mloc[2 * jp + 1], s1);
            }
        }
#pragma unroll
        for (int jj = 0; jj < 8; jj++) {
            float m = mloc[jj];
#pragma unroll
            for (int off = 8; off >= 1; off >>= 1)
                m = fmaxf(m, __shfl_xor_sync(0xFFFFFFFFu, m, off));
            if (rg == 0) atomicMax(&g_bmax[cg * 8 + jj], fenc(m));
        }
    } else {
#pragma unroll
        for (int i = 0; i < 8; i++) {
            int r = rg + i * 16;
            int s = row0 + r;
            float2 p0 = *reinterpret_cast<float2*>(&acc[i][0]);
            float2 p1 = *reinterpret_cast<float2*>(&acc[i][1]);
            float2 p2 = *reinterpret_cast<float2*>(&acc[i][2]);
            float2 p3 = *reinterpret_cast<float2*>(&acc[i][3]);
            float4 q0 = make_float4(p0.x, p0.y, p1.x, p1.y);
            float4 q1 = make_float4(p2.x, p2.y, p3.x, p3.y);
            float* base = g_confdot + (size_t)s * 32 + (cg - 8) * 8;
            *(float4*)(base) = q0;
            *(float4*)(base + 4) = q1;
        }
    }
}

// ---------------- 5: age max ----------------
__global__ void k_agemax(const float* __restrict__ at) {
    int s = blockIdx.x * 256 + threadIdx.x;
    int t = threadIdx.x;
    __shared__ unsigned sh[256];
    float age = fmaxf(g_s.stepf - at[s], 0.f);
    sh[t] = __float_as_uint(age);
    __syncthreads();
    for (int off = 128; off > 0; off >>= 1) {
        if (t < off && sh[t + off] > sh[t]) sh[t] = sh[t + off];
        __syncthreads();
    }
    if (t == 0) atomicMax(&g_s.age_max_bits, sh[0]);
}

// ---------------- 6: store gate path (k-split, vector weight loads) ----------------
__global__ void k_store(const float* __restrict__ nc, const float* __restrict__ q,
                        const float* __restrict__ sr_w1, const float* __restrict__ sr_b1,
                        const float* __restrict__ sr_g,  const float* __restrict__ sr_beta,
                        const float* __restrict__ sr_w2, const float* __restrict__ sr_b2,
                        const float* __restrict__ sn_w,  const float* __restrict__ sn_b,
                        const float* __restrict__ sg_w,  const float* __restrict__ sg_b,
                        float* __restrict__ out_store) {
    int b = blockIdx.x, t = threadIdx.x;   // 256 threads
    __shared__ float comb[1024];
    __shared__ float hpart[4][256];
    __shared__ float rh[256];
    __shared__ float red[256];
    __shared__ float r2part[2][128];
    __shared__ float nfpart[2][128];
    for (int i = t; i < 512; i += 256) {
        comb[i] = nc[b * 512 + i];
        comb[512 + i] = q[b * 512 + i];
    }
    __syncthreads();
    int ks = t >> 6, cg = t & 63;
    // phase 1: H = comb @ sr_w1 (each thread: 4 cols, 256-k slice)
    {
        float4 a = make_float4(0.f, 0.f, 0.f, 0.f);
        const float* wp = sr_w1 + 4 * cg;
        for (int k = ks * 256; k < ks * 256 + 256; k++) {
            float4 w = *(const float4*)(wp + (size_t)k * 256);
            float x = comb[k];
            a.x = fmaf(x, w.x, a.x); a.y = fmaf(x, w.y, a.y);
            a.z = fmaf(x, w.z, a.z); a.w = fmaf(x, w.w, a.w);
        }
        ((float4*)&hpart[ks][0])[cg] = a;
    }
    __syncthreads();
    float h = hpart[0][t] + hpart[1][t] + hpart[2][t] + hpart[3][t] + sr_b1[t];
    // LN over 256
    red[t] = h; __syncthreads();
    for (int off = 128; off > 0; off >>= 1) { if (t < off) red[t] += red[t + off]; __syncthreads(); }
    float m = red[0] / 256.0f; __syncthreads();
    float d = h - m;
    red[t] = d * d; __syncthreads();
    for (int off = 128; off > 0; off >>= 1) { if (t < off) red[t] += red[t + off]; __syncthreads(); }
    float var = red[0] / 256.0f; __syncthreads();
    float hn = d * rsqrtf(var + 1e-5f) * sr_g[t] + sr_beta[t];
    rh[t] = fmaxf(hn, 0.f);
    __syncthreads();
    // phase 2a: rel = relu(rh @ sr_w2): 2 k-slices x 128 cols
    {
        int ks2 = t >> 7, c = t & 127;
        float a = 0.f;
        for (int k = ks2 * 128; k < ks2 * 128 + 128; k++)
            a = fmaf(rh[k], sr_w2[(size_t)k * 128 + c], a);
        r2part[ks2][c] = a;
    }
    // phase 2b: nf-dot: 2 k-slices (256 each) x 128 cols
    {
        int ks2 = t >> 7, c = t & 127;
        float a = 0.f;
        for (int k = ks2 * 256; k < ks2 * 256 + 256; k++)
            a = fmaf(comb[k], sn_w[(size_t)k * 128 + c], a);
        nfpart[ks2][c] = a;
    }
    __syncthreads();
    float val = 0.f;
    if (t < 128) {
        float r = fmaxf(r2part[0][t] + r2part[1][t] + sr_b2[t], 0.f);
        float nf = sigf(nfpart[0][t] + nfpart[1][t] + sn_b[t]);
        val = (r + nf) * sg_w[t];
    }
    red[t] = val; __syncthreads();
    for (int off = 128; off > 0; off >>= 1) { if (t < off) red[t] += red[t + off]; __syncthreads(); }
    if (t == 0) {
        float sc = sigf(red[0] + sg_b[0]);
        g_storev[b] = sc;
        out_store[b] = sc;
    }
}

// ---------------- 7: n_active + victim ----------------
__global__ void k_act_vic(const float* __restrict__ at) {
    int s = blockIdx.x * 256 + threadIdx.x;
    int t = threadIdx.x;
    __shared__ int shi[256];
    __shared__ unsigned long long sh[256];
    float nrm = g_norms[s];
    shi[t] = (nrm > 0.5f) ? 1 : 0;
    float amax = __uint_as_float(g_s.age_max_bits);
    float age = fmaxf(g_s.stepf - at[s], 0.f);
    float es = age / (amax + 1e-6f) + (1.0f - sigf(nrm));
    sh[t] = ((unsigned long long)fenc(es) << 32) | (unsigned long long)(0xFFFFFFFFu - (unsigned)s);
    __syncthreads();
    for (int off = 128; off > 0; off >>= 1) {
        if (t < off) {
            shi[t] += shi[t + off];
            if (sh[t + off] > sh[t]) sh[t] = sh[t + off];
        }
        __syncthreads();
    }
    if (t == 0) {
        atomicAdd(&g_s.n_active, shi[0]);
        atomicMax(&g_s.victim_pack, sh[0]);
    }
}

// ---------------- 8: scalars + novelty ----------------
__global__ void k_fin1(float* __restrict__ out_nov) {
    int t = threadIdx.x;   // 64 threads
    __shared__ float red[64];
    float nov = (1.0f - fdec(g_bmax[t])) * 0.5f;
    out_nov[t] = nov;
    red[t] = nov; __syncthreads();
    for (int off = 32; off > 0; off >>= 1) { if (t < off) red[t] += red[t + off]; __syncthreads(); }
    if (t == 0) {
        g_s.nov_mean = red[0] / (float)BATCH;
        float cap = (float)g_s.n_active / (float)S_SLOTS;
        g_s.do_erase = (cap > 0.85f) ? 1 : 0;
        float dyn = (cap < 0.3f) ? 0.08f : ((cap < 0.6f) ? 0.08f + (cap - 0.3f) * 0.733f
                                                         : 0.3f + (cap - 0.6f));
        g_s.dyn_thr = fminf(fmaxf(dyn, 0.0f), 0.7f);
        g_s.topk_thr = (cap < 0.3f) ? 0.1f : ((cap < 0.6f) ? 0.2f : 0.4f);
        g_s.raw_thr = (cap < 0.3f) ? 0.3f : 0.5f;
        g_s.victim = (int)(0xFFFFFFFFu - (unsigned)(g_s.victim_pack & 0xFFFFFFFFull));
    }
}

// ---------------- 9: partial top3 + perc scan (4 blocks per b) ----------------
__device__ __forceinline__ bool better(float av, int ai, float bv, int bi) {
    return (av > bv) || (av == bv && ai < bi);
}
__global__ void k_scan_part() {
    int b = blockIdx.x >> 2, qt = blockIdx.x & 3;
    int t = threadIdx.x;   // 256
    int base = qt * 16384;
    int de = g_s.do_erase, vic = g_s.victim;
    float nm = g_s.nov_mean;
    float v0 = -FLT_MAX, v1 = -FLT_MAX, v2 = -FLT_MAX;
    int i0 = 0x7FFFFFFF, i1 = 0x7FFFFFFF, i2 = 0x7FFFFFFF;
    int cnt = 0;
    const float* row = g_sims + (size_t)b * S_SLOTS;
    for (int s = base + t; s < base + 16384; s += 256) {
        float vraw = row[s];
        if ((nm > 1.0f - vraw) && (g_norms[s] > 0.5f)) cnt++;
        float v = (de && s == vic) ? 0.f : vraw;
        if (better(v, s, v2, i2)) {
            if (better(v, s, v1, i1)) {
                if (better(v, s, v0, i0)) { v2=v1;i2=i1; v1=v0;i1=i0; v0=v;i0=s; }
                else                      { v2=v1;i2=i1; v1=v; i1=s; }
            } else                        { v2=v; i2=s; }
        }
    }
    __shared__ float sv[256 * 3];
    __shared__ int   si[256 * 3];
    __shared__ int   sc[256];
    sv[t*3+0]=v0; sv[t*3+1]=v1; sv[t*3+2]=v2;
    si[t*3+0]=i0; si[t*3+1]=i1; si[t*3+2]=i2;
    sc[t] = cnt;
    __syncthreads();
    for (int off = 128; off > 0; off >>= 1) { if (t < off) sc[t] += sc[t + off]; __syncthreads(); }
    if (t == 0) {
        atomicAdd(&g_s.cond_count, sc[0]);
        float w0=-FLT_MAX,w1=-FLT_MAX,w2=-FLT_MAX; int j0=0x7FFFFFFF,j1=0x7FFFFFFF,j2=0x7FFFFFFF;
        for (int e = 0; e < 256 * 3; e++) {
            float v = sv[e]; int s = si[e];
            if (better(v, s, w2, j2)) {
                if (better(v, s, w1, j1)) {
                    if (better(v, s, w0, j0)) { w2=w1;j2=j1; w1=w0;j1=j0; w0=v;j0=s; }
                    else                      { w2=w1;j2=j1; w1=v; j1=s; }
                } else                        { w2=v; j2=s; }
            }
        }
        int o = (b * 4 + qt) * 3;
        g_p3v[o+0]=w0; g_p3v[o+1]=w1; g_p3v[o+2]=w2;
        g_p3i[o+0]=j0; g_p3i[o+1]=j1; g_p3i[o+2]=j2;
    }
}

// ---------------- 10: merge quarter top3s ----------------
__global__ void k_top3m() {
    int b = threadIdx.x;   // 64 threads
    float w0=-FLT_MAX,w1=-FLT_MAX,w2=-FLT_MAX;
    int j0=0x7FFFFFFF,j1=0x7FFFFFFF,j2=0x7FFFFFFF;
    for (int e = 0; e < 12; e++) {
        float v = g_p3v[b*12+e]; int s = g_p3i[b*12+e];
        if (better(v, s, w2, j2)) {
            if (better(v, s, w1, j1)) {
                if (better(v, s, w0, j0)) { w2=w1;j2=j1; w1=w0;j1=j0; w0=v;j0=s; }
                else                      { w2=w1;j2=j1; w1=v; j1=s; }
            } else                        { w2=v; j2=s; }
        }
    }
    g_tv[b*3+0]=w0; g_tv[b*3+1]=w1; g_tv[b*3+2]=w2;
    g_ti[b*3+0]=j0; g_ti[b*3+1]=j1; g_ti[b*3+2]=j2;
}

// ---------------- 11: pair MLPs (4 pairs x col-half per block, 96 blocks) ----------------
__global__ void k_pair(const float* __restrict__ nc, const float* __restrict__ mem,
                       const float* __restrict__ dd_w1, const float* __restrict__ dd_b1,
                       const float* __restrict__ dd_w2,
                       const float* __restrict__ ds_w1, const float* __restrict__ ds_b1,
                       const float* __restrict__ ds_w2) {
    __shared__ float pr[4][1024];
    __shared__ float2 part[4][4][2][64];   // [ks][pair][net][colpair]
    __shared__ float red[256];
    int t = threadIdx.x;   // 256
    int pg = blockIdx.x >> 1, ch = blockIdx.x & 1;
    int p0 = pg * 4;
    int de = g_s.do_erase, vic = g_s.victim;
    for (int p = 0; p < 4; p++) {
        int pi = p0 + p;
        int b = pi / 3;
        int ti = g_ti[pi];
        bool z = (de && ti == vic);
        for (int i = t; i < 512; i += 256) {
            pr[p][i] = nc[b * 512 + i];
            pr[p][512 + i] = z ? 0.f : mem[(size_t)ti * 512 + i];
        }
    }
    __syncthreads();
    int ks = t >> 6, cg = t & 63;
    int colG = ch * 128 + 2 * cg;
    unsigned long long aD[4] = {0ull,0ull,0ull,0ull};
    unsigned long long aS[4] = {0ull,0ull,0ull,0ull};
    const float* dp = dd_w1 + colG;
    const float* sp = ds_w1 + colG;
    for (int k = ks * 256; k < ks * 256 + 256; k++) {
        unsigned long long wd = *(const unsigned long long*)(dp + (size_t)k * 256);
        unsigned long long ws = *(const unsigned long long*)(sp + (size_t)k * 256);
#pragma unroll
        for (int p = 0; p < 4; p++) {
            float x = pr[p][k];
            unsigned xi = __float_as_uint(x);
            unsigned long long x2;
            asm("mov.b64 %0, {%1, %2};" : "=l"(x2) : "r"(xi), "r"(xi));
            asm("fma.rn.f32x2 %0, %1, %2, %0;" : "+l"(aD[p]) : "l"(x2), "l"(wd));
            asm("fma.rn.f32x2 %0, %1, %2, %0;" : "+l"(aS[p]) : "l"(x2), "l"(ws));
        }
    }
#pragma unroll
    for (int p = 0; p < 4; p++) {
        part[ks][p][0][cg] = *reinterpret_cast<float2*>(&aD[p]);
        part[ks][p][1][cg] = *reinterpret_cast<float2*>(&aS[p]);
    }
    __syncthreads();
    float vals[8];
    if (t < 128) {
        int c = t;            // local col
        int cG = ch * 128 + c;
#pragma unroll
        for (int p = 0; p < 4; p++) {
#pragma unroll
            for (int net = 0; net < 2; net++) {
                float s = 0.f;
#pragma unroll
                for (int kq = 0; kq < 4; kq++) {
                    float2 f2 = part[kq][p][net][c >> 1];
                    s += (c & 1) ? f2.y : f2.x;
                }
                s += net ? ds_b1[cG] : dd_b1[cG];
                s = fmaxf(s, 0.f) * (net ? ds_w2[cG] : dd_w2[cG]);
                vals[p * 2 + net] = s;
            }
        }
    }
    for (int pn = 0; pn < 8; pn++) {
        __syncthreads();
        red[t] = (t < 128) ? vals[pn] : 0.f;
        __syncthreads();
        for (int off = 128; off > 0; off >>= 1) { if (t < off) red[t] += red[t + off]; __syncthreads(); }
        if (t == 0) atomicAdd(&g_pairacc[(p0 + (pn >> 1)) * 2 + (pn & 1)], red[0]);
    }
}

// ---------------- 12: erase scores + masked max + dual argmax ----------------
__global__ void k_erase1(const float* __restrict__ at,
                         const float* __restrict__ el_w, const float* __restrict__ el_b,
                         const float* __restrict__ ec_b,
                         const float* __restrict__ eg_w, const float* __restrict__ eg_b) {
    int s = blockIdx.x * 256 + threadIdx.x;
    int t = threadIdx.x;
    __shared__ unsigned shm[256];
    __shared__ unsigned long long pm[256];
    __shared__ unsigned long long pa[256];
    int de = g_s.do_erase, vic = g_s.victim;
    float atv = at[s];
    bool zv = (de && s == vic);
    if (zv) atv = -99999.0f;
    float x = (g_s.stepf - atv) * 0.001f;
    float acc = eg_b[0];
    const float4* cd4 = (const float4*)(g_confdot + (size_t)s * 32);
#pragma unroll
    for (int jq = 0; jq < 8; jq++) {
        float4 cd = cd4[jq];
        float cda[4] = {cd.x, cd.y, cd.z, cd.w};
#pragma unroll
        for (int r = 0; r < 4; r++) {
            int j = jq * 4 + r;
            float lru = fmaxf(fmaf(x, el_w[j], el_b[j]), 0.f);
            float c = zv ? 0.f : cda[r];
            float conf = sigf(c + ec_b[j]);
            acc += lru * eg_w[j] + conf * eg_w[32 + j];
        }
    }
    float e = sigf(acc);
    g_erase[s] = e;
    float sa = g_s.stepf - atv;
    g_slotage[s] = sa;
    bool recent = (atv >= 0.f) && (sa < 3.f);
    float mp = recent ? 0.f : e;
    g_maskedpre[s] = mp;
    unsigned idxe = 0xFFFFFFFFu - (unsigned)s;
    shm[t] = __float_as_uint(mp);
    pm[t] = ((unsigned long long)fenc(mp) << 32) | (unsigned long long)idxe;
    pa[t] = ((unsigned long long)fenc(sa) << 32) | (unsigned long long)idxe;
    __syncthreads();
    for (int off = 128; off > 0; off >>= 1) {
        if (t < off) {
            if (shm[t + off] > shm[t]) shm[t] = shm[t + off];
            if (pm[t + off] > pm[t]) pm[t] = pm[t + off];
            if (pa[t + off] > pa[t]) pa[t] = pa[t + off];
        }
        __syncthreads();
    }
    if (t == 0) {
        atomicMax(&g_s.masked_max_bits, shm[0]);
        atomicMax(&g_s.wpack_m, pm[0]);
        atomicMax(&g_s.wpack_a, pa[0]);
    }
}

// ---------------- 13: finalize decisions + drift + patch rows ----------------
__global__ void k_finalize(const float* __restrict__ nc, const float* __restrict__ mem,
                           const float* __restrict__ dd_b2, const float* __restrict__ ds_b2,
                           float* __restrict__ out_mem) {
    int t = threadIdx.x;  // 512 threads
    if (t < BATCH * 3) {
        float prob = sigf(g_pairacc[t * 2 + 0] + dd_b2[0]);
        float st   = sigf(g_pairacc[t * 2 + 1] + ds_b2[0]);
        g_strength[t] = st;
        float tv = g_tv[t];
        g_apply[t] = (tv > 0.7f && tv < 0.99f && prob > 0.5f) ? 1 : 0;
    }
    __syncthreads();
    if (t == 0) {
        float ssum = 0.f;
        for (int b = 0; b < BATCH; b++) ssum += g_storev[b];
        float smean = ssum / (float)BATCH;
        int na = g_s.n_active;
        int nam = na > 1 ? na : 1;
        float perc = (na > 0) ? ((float)g_s.cond_count / (64.0f * (float)nam)) : 1.0f;
        bool base = smean > g_s.raw_thr;
        bool novok = g_s.nov_mean > g_s.dyn_thr;
        bool topok = perc > g_s.topk_thr;
        bool ss = base && novok && topok;
        if (g_s.do_erase && !novok) ss = false;
        g_s.should_store = ss ? 1 : 0;
        int usa = (__uint_as_float(g_s.masked_max_bits) <= 0.0f) ? 1 : 0;
        g_s.use_slotage = usa;
        unsigned long long wp = usa ? g_s.wpack_a : g_s.wpack_m;
        int wmax = (int)(0xFFFFFFFFu - (unsigned)(wp & 0xFFFFFFFFull));
        int wi = g_s.do_erase ? g_s.victim : wmax;
        g_s.write_idx = wi;
        int n = 0;
        if (g_s.do_erase) g_chg[n++] = g_s.victim;
        for (int p = 0; p < BATCH * 3; p++) {
            if (g_apply[p]) {
                int r = g_ti[p];
                int found = 0;
                for (int j = 0; j < n; j++) if (g_chg[j] == r) { found = 1; break; }
                if (!found) g_chg[n++] = r;
            }
        }
        if (ss) {
            int r = wi, found = 0;
            for (int j = 0; j < n; j++) if (g_chg[j] == r) { found = 1; break; }
            if (!found) g_chg[n++] = r;
        }
        g_nchg = n;
    }
    __syncthreads();
    int de = g_s.do_erase, vic = g_s.victim;
    float nc0 = nc[t];
    float v = nc0;
    for (int k = 0; k < 3; k++) {
        if (g_apply[k]) {
            int r = g_ti[k];
            float g = (de && r == vic) ? 0.f : mem[(size_t)r * 512 + t];
            float st = g_strength[k];
            float avg = 0.5f * (nc0 + g);
            v = (1.f - st) * nc0 + st * avg;
        }
    }
    g_drifted0[t] = v;
    if (de) out_mem[(size_t)vic * 512 + t] = 0.f;
    for (int k = 0; k < 3; k++) {
        for (int b = 0; b < BATCH; b++) {
            int p = b * 3 + k;
            if (g_apply[p]) {
                int r = g_ti[p];
                float g = (de && r == vic) ? 0.f : mem[(size_t)r * 512 + t];
                float st = g_strength[p];
                float ncv = nc[b * 512 + t];
                float avg = 0.5f * (ncv + g);
                out_mem[(size_t)r * 512 + t] = (1.f - st) * g + st * avg;
            }
        }
    }
    if (g_s.should_store) out_mem[(size_t)g_s.write_idx * 512 + t] = g_drifted0[t];
}

// ---------------- 14: at + erase outputs ----------------
__global__ void k_outputs(const float* __restrict__ at,
                          float* __restrict__ out_at, float* __restrict__ out_erase) {
    int s = blockIdx.x * 256 + threadIdx.x;
    float atv = at[s];
    if (g_s.do_erase && s == g_s.victim) atv = -99999.0f;
    if (g_s.should_store && s == g_s.write_idx) atv = g_s.stepf;
    out_at[s] = atv;
    float mf = g_s.use_slotage ? g_slotage[s] : g_maskedpre[s];
    out_erase[s] = (g_s.should_store && !g_s.do_erase) ? mf : g_erase[s];
}

// ---------------- 15: recent_changes (sparse) ----------------
__global__ void k_rc(const float* __restrict__ mem, const float* __restrict__ out_mem,
                     float* __restrict__ out_rc) {
    int t = threadIdx.x;  // 256
    __shared__ float sh[256];
    int n = g_nchg;
    float s = 0.f;
    for (int j = t; j < n * 512; j += 256) {
        int r = g_chg[j >> 9];
        int d = j & 511;
        s += fabsf(out_mem[(size_t)r * 512 + d] - mem[(size_t)r * 512 + d]);
    }
    sh[t] = s; __syncthreads();
    for (int off = 128; off > 0; off >>= 1) { if (t < off) sh[t] += sh[t + off]; __syncthreads(); }
    if (t == 0) out_rc[0] = sh[0] / ((float)S_SLOTS * (float)DIM);
}

// ---------------- launch ----------------
extern "C" void kernel_launch(void* const* d_in, const int* in_sizes, int n_in,
                              void* d_out, int out_size) {
    bool dictOrder = (in_sizes[4] == 1);
    const float* nc   = (const float*)d_in[0];
    const float* q    = (const float*)d_in[1];
    const float* mem  = (const float*)d_in[2];
    const float* at   = (const float*)d_in[3];
    int base = dictOrder ? 5 : 4;
    const float* sr_w1 = (const float*)d_in[base + 0];
    const float* sr_b1 = (const float*)d_in[base + 1];
    const float* sr_g  = (const float*)d_in[base + 2];
    const float* sr_be = (const float*)d_in[base + 3];
    const float* sr_w2 = (const float*)d_in[base + 4];
    const float* sr_b2 = (const float*)d_in[base + 5];
    const float* sn_w  = (const float*)d_in[base + 6];
    const float* sn_b  = (const float*)d_in[base + 7];
    const float* sg_w  = (const float*)d_in[base + 8];
    const float* sg_b  = (const float*)d_in[base + 9];
    const float* el_w  = (const float*)d_in[base + 10];
    const float* el_b  = (const float*)d_in[base + 11];
    const float* ec_w  = (const float*)d_in[base + 12];
    const float* ec_b  = (const float*)d_in[base + 13];
    const float* eg_w  = (const float*)d_in[base + 14];
    const float* eg_b  = (const float*)d_in[base + 15];
    const float* dd_w1 = (const float*)d_in[base + 16];
    const float* dd_b1 = (const float*)d_in[base + 17];
    const float* dd_w2 = (const float*)d_in[base + 18];
    const float* dd_b2 = (const float*)d_in[base + 19];
    const float* ds_w1 = (const float*)d_in[base + 20];
    const float* ds_b1 = (const float*)d_in[base + 21];
    const float* ds_w2 = (const float*)d_in[base + 22];
    const float* ds_b2 = (const float*)d_in[base + 23];
    const void*  step  = dictOrder ? d_in[4] : d_in[28];

    float* out_mem   = (float*)d_out;
    float* out_at    = out_mem + (size_t)S_SLOTS * DIM;
    float* out_erase = out_at + S_SLOTS;
    float* out_store = out_erase + S_SLOTS;
    float* out_nov   = out_store + BATCH;
    float* out_rc    = out_nov + BATCH;

    k_reset<<<1, 384>>>(step);                                  // 1
    k_norm_a<<<BATCH, 128>>>(nc);                               // 2
    k_norm_b<<<DIM, BATCH>>>(nc);                               // 3
    k_main<<<S_SLOTS / 128, 192>>>(mem, ec_w, out_mem);         // 4  <- ncu capture slot
    k_agemax<<<S_SLOTS / 256, 256>>>(at);                       // 5
    k_store<<<BATCH, 256>>>(nc, q, sr_w1, sr_b1, sr_g, sr_be,   // 6
                            sr_w2, sr_b2, sn_w, sn_b, sg_w, sg_b, out_store);
    k_act_vic<<<S_SLOTS / 256, 256>>>(at);                      // 7
    k_fin1<<<1, 64>>>(out_nov);                                 // 8
    k_scan_part<<<BATCH * 4, 256>>>();                          // 9
    k_top3m<<<1, 64>>>();                                       // 10
    k_pair<<<96, 256>>>(nc, mem, dd_w1, dd_b1, dd_w2,           // 11
                        ds_w1, ds_b1, ds_w2);
    k_erase1<<<S_SLOTS / 256, 256>>>(at, el_w, el_b, ec_b, eg_w, eg_b); // 12
    k_finalize<<<1, 512>>>(nc, mem, dd_b2, ds_b2, out_mem);     // 13
    k_outputs<<<S_SLOTS / 256, 256>>>(at, out_at, out_erase);   // 14
    k_rc<<<1, 256>>>(mem, out_mem, out_rc);                     // 15
}